// round 15
// baseline (speedup 1.0000x reference)
#include <cuda_runtime.h>
#include <cuda_bf16.h>
#include <cstdint>

// BitLevelMapper: B=4194304 rows x 16 bits.
// bits:   [B,16] int32 {0,1}  (d_in[0])
// tables: [16, 32768] float32 {0,1} (d_in[1])
// out:    [B,16] float32
//
// R15: oct-per-thread with 256-bit LDG/STG (sm_100a+ ld/st.global.v8.b32).
// One 32B load per thread = warp-wide 1024B fully sector-packed (fixes the
// R13 stride-2 regression), half the iterations, ONE shfl_xor per oct.
// Ballot pack + PDL + pre-sync hoist + full-wave grid kept from R12/R14.

#define NBITS   16
#define TSIZE   32768           // 2^15 entries per table row
#define NWORDS  2052            // sum over i of ceil(max(2^i,32)/32)

__device__ uint32_t g_packed[NWORDS];

// word offset of table row i in the packed layout
__host__ __device__ __forceinline__ int tab_off(int i) {
    return (i < 5) ? i : ((1 << (i - 5)) + 4);
}

// One warp per packed word: lane b reads entry lw*32+b, ballot packs.
__global__ void pack_tables_kernel(const float* __restrict__ tables) {
    int gw   = (blockIdx.x * blockDim.x + threadIdx.x) >> 5;
    int lane = threadIdx.x & 31;
    if (gw < NWORDS) {
        int i = 0;
        #pragma unroll
        for (int r = 1; r < 16; r++)
            if (gw >= tab_off(r)) i = r;
        int lw = gw - tab_off(i);
        float v = tables[(size_t)i * TSIZE + lw * 32 + lane];
        unsigned word = __ballot_sync(0xffffffffu, v != 0.0f);
        if (lane == 0) g_packed[gw] = word;
    }
    __threadfence();                              // order g_packed before signal
    cudaTriggerProgrammaticLaunchCompletion();    // release dependent launch early
}

#define MAP_BLOCKS  1216        // 152 SMs x 8 CTAs: one full resident wave
#define MAP_THREADS 256

// 256-bit global load/store (sm_100a+ PTX .v8.b32, 32B-aligned)
__device__ __forceinline__ void ldg256(const uint32_t* p, uint32_t r[8]) {
    asm volatile("ld.global.v8.b32 {%0,%1,%2,%3,%4,%5,%6,%7}, [%8];"
        : "=r"(r[0]), "=r"(r[1]), "=r"(r[2]), "=r"(r[3]),
          "=r"(r[4]), "=r"(r[5]), "=r"(r[6]), "=r"(r[7])
        : "l"(p));
}
__device__ __forceinline__ void stg256(uint32_t* p, const uint32_t r[8]) {
    asm volatile("st.global.v8.b32 [%0], {%1,%2,%3,%4,%5,%6,%7,%8};"
        :: "l"(p),
           "r"(r[0]), "r"(r[1]), "r"(r[2]), "r"(r[3]),
           "r"(r[4]), "r"(r[5]), "r"(r[6]), "r"(r[7])
        : "memory");
}

// Process one oct (8 int32 = half a row). shift = 15 - 8*(t&1).
__device__ __forceinline__ void oct_out(
    const uint32_t r[8], int shift, const uint32_t* __restrict__ s_tab,
    uint32_t o[8])
{
    // partial pattern: value m (j = 8p+m) sits at bit position shift-m
    unsigned P = (r[0] << shift)       | (r[1] << (shift - 1))
               | (r[2] << (shift - 2)) | (r[3] << (shift - 3))
               | (r[4] << (shift - 4)) | (r[5] << (shift - 5))
               | (r[6] << (shift - 6)) | (r[7] << (shift - 7));
    // single OR-exchange with the partner lane completes the 16-bit pattern
    P |= __shfl_xor_sync(0xffffffffu, P, 1);

    #pragma unroll
    for (int m = 0; m < 8; m++) {
        int i = shift - m;                             // table row index
        unsigned addr = P & ((1u << i) - 1u);          // prefix of context
        uint32_t wv = s_tab[tab_off(i) + (addr >> 5)];
        unsigned x = ((wv >> (addr & 31u)) ^ (P >> i)) & 1u;   // bit ^ flip
        o[m] = (0u - x) & 0x3f800000u;                 // x ? 1.0f : 0.0f (bits)
    }
}

__global__ void __launch_bounds__(MAP_THREADS, 8)
map_kernel(const uint32_t* __restrict__ bits, uint32_t* __restrict__ out,
           int nocts) {
    const int stride = gridDim.x * blockDim.x;
    const int base_t = blockIdx.x * blockDim.x + threadIdx.x;
    const int p      = base_t & 1;            // oct parity within the row
    const int shift  = 15 - 8 * p;            // bit position of r[0] in P
    const int nmain  = nocts / stride;        // uniform across all threads

    // First input load is independent of the pack — issue it before the
    // dependency sync so the wait overlaps the DRAM fetch.
    uint32_t v0[8];
    ldg256(bits + (size_t)base_t * 8, v0);

    cudaGridDependencySynchronize();          // g_packed now valid

    __shared__ uint32_t s_tab[NWORDS];
    for (int t = threadIdx.x; t < NWORDS; t += blockDim.x)
        s_tab[t] = g_packed[t];
    __syncthreads();

    // iteration 0 (peeled, uses the pre-sync load)
    {
        uint32_t o[8];
        oct_out(v0, shift, s_tab, o);
        stg256(out + (size_t)base_t * 8, o);
    }

    // iterations 1..nmain; residual predicate is warp-uniform
    // ((nocts % stride) % 32 == 0) so the shuffle path is safe in the tail.
    for (int it = 1; it <= nmain; it++) {
        int t = base_t + it * stride;
        if (t >= nocts) break;                // warp-uniform exit
        uint32_t v[8], o[8];
        ldg256(bits + (size_t)t * 8, v);
        oct_out(v, shift, s_tab, o);
        stg256(out + (size_t)t * 8, o);
    }
}

extern "C" void kernel_launch(void* const* d_in, const int* in_sizes, int n_in,
                              void* d_out, int out_size) {
    const uint32_t* bits   = (const uint32_t*)d_in[0];
    const float*    tables = (const float*)d_in[1];
    uint32_t*       out    = (uint32_t*)d_out;

    int nocts = in_sizes[0] / 8;       // 8388608

    pack_tables_kernel<<<(NWORDS * 32 + 255) / 256, 256>>>(tables);

    cudaLaunchConfig_t cfg = {};
    cfg.gridDim  = dim3(MAP_BLOCKS, 1, 1);
    cfg.blockDim = dim3(MAP_THREADS, 1, 1);
    cfg.dynamicSmemBytes = 0;
    cfg.stream = 0;                    // legacy default stream (capture target)
    cudaLaunchAttribute attr[1];
    attr[0].id = cudaLaunchAttributeProgrammaticStreamSerialization;
    attr[0].val.programmaticStreamSerializationAllowed = 1;
    cfg.attrs = attr;
    cfg.numAttrs = 1;
    cudaLaunchKernelEx(&cfg, map_kernel, bits, out, nocts);
}

// round 16
// speedup vs baseline: 1.1991x; 1.1991x over previous
#include <cuda_runtime.h>
#include <cuda_bf16.h>
#include <cstdint>

// BitLevelMapper: B=4194304 rows x 16 bits.
// bits:   [B,16] int32 {0,1}  (d_in[0])
// tables: [16, 32768] float32 {0,1} (d_in[1])
// out:    [B,16] float32
//
// FINAL (= R12, best verified 88.58us). Design, each element bench-proven:
//  - quad-per-thread: 4 lanes/row, LDG/STG.128 fully sector-packed (R2);
//    oct layouts falsified twice (R13 sectors, R15 v8 reg-alignment).
//  - 8.2KB packed-bit table in smem, 4 LDS + shift per quad (R5);
//    fused LUT / fewer instructions: neutral (R6).
//  - grid = 1216 = 152 SMs x 8 CTAs = one full resident wave (R5);
//    MLP/prefetch/unroll falsified x3 (R3/R4/R7); .cs hints neutral (R8).
//  - warp-uniform quad tail, no scalar re-read amplification (R8/R9).
//  - PDL: pack triggers completion early; map hoists its first input load
//    above cudaGridDependencySynchronize (R10/R12) -> ~6.9us overhead floor.
// Map moves 512MiB at ~6.3TB/s = ~95% of the B300 mixed-stream LTS cap.

#define NBITS   16
#define TSIZE   32768           // 2^15 entries per table row
#define NWORDS  2052            // sum over i of ceil(max(2^i,32)/32)

__device__ uint32_t g_packed[NWORDS];

// word offset of table row i in the packed layout
__host__ __device__ __forceinline__ int tab_off(int i) {
    return (i < 5) ? i : ((1 << (i - 5)) + 4);
}

// One warp per packed word: lane b reads entry lw*32+b, ballot packs.
__global__ void pack_tables_kernel(const float* __restrict__ tables) {
    int gw   = (blockIdx.x * blockDim.x + threadIdx.x) >> 5;
    int lane = threadIdx.x & 31;
    if (gw < NWORDS) {
        int i = 0;
        #pragma unroll
        for (int r = 1; r < 16; r++)
            if (gw >= tab_off(r)) i = r;
        int lw = gw - tab_off(i);
        float v = tables[(size_t)i * TSIZE + lw * 32 + lane];
        unsigned word = __ballot_sync(0xffffffffu, v != 0.0f);
        if (lane == 0) g_packed[gw] = word;
    }
    __threadfence();                              // order g_packed before signal
    cudaTriggerProgrammaticLaunchCompletion();    // release dependent launch early
}

#define MAP_BLOCKS  1216        // 152 SMs x 8 CTAs: one full resident wave
#define MAP_THREADS 256

__device__ __forceinline__ float4 quad_out(
    int4 v, int shift, const uint32_t* __restrict__ s_tab)
{
    // partial 16-bit pattern: bit j (array order) sits at position 15-j
    unsigned P = ((unsigned)v.x << shift)       | ((unsigned)v.y << (shift - 1))
               | ((unsigned)v.z << (shift - 2)) | ((unsigned)v.w << (shift - 3));
    // OR-reduce across the aligned 4-lane group -> full pattern in all 4 lanes
    P |= __shfl_xor_sync(0xffffffffu, P, 1);
    P |= __shfl_xor_sync(0xffffffffu, P, 2);

    float o[4];
    #pragma unroll
    for (int m = 0; m < 4; m++) {
        int i = shift - m;                             // table row index
        unsigned addr = P & ((1u << i) - 1u);          // prefix of context
        uint32_t wv = s_tab[tab_off(i) + (addr >> 5)];
        unsigned x = ((wv >> (addr & 31u)) ^ (P >> i)) & 1u;   // bit ^ flip
        o[m] = __uint_as_float((0u - x) & 0x3f800000u);        // x ? 1.0f : 0.0f
    }
    return make_float4(o[0], o[1], o[2], o[3]);
}

__global__ void __launch_bounds__(MAP_THREADS, 8)
map_kernel(const int4* __restrict__ bits4, float4* __restrict__ out4, int nquads) {
    const int stride = gridDim.x * blockDim.x;
    const int base_t = blockIdx.x * blockDim.x + threadIdx.x;
    const int q      = base_t & 3;           // quarter within row (lane-group pos)
    const int shift  = 15 - 4 * q;           // bit position of v.x in pattern P
    const int nmain  = nquads / stride;      // uniform across all threads

    // First input load is independent of the pack — issue it before the
    // dependency sync so the wait overlaps the DRAM fetch.
    int4 v0 = bits4[base_t];                 // base_t < nquads always here

    cudaGridDependencySynchronize();         // g_packed now valid

    __shared__ uint32_t s_tab[NWORDS];
    for (int t = threadIdx.x; t < NWORDS; t += blockDim.x)
        s_tab[t] = g_packed[t];
    __syncthreads();

    // iteration 0 (peeled, uses the pre-sync load)
    out4[base_t] = quad_out(v0, shift, s_tab);

    // iterations 1..nmain; residual predicate is warp-uniform
    // ((nquads % stride) % 32 == 0) so the shuffle path is safe in the tail.
    for (int it = 1; it <= nmain; it++) {
        int t = base_t + it * stride;
        if (t >= nquads) break;              // warp-uniform exit
        int4 v = bits4[t];
        out4[t] = quad_out(v, shift, s_tab);
    }
}

extern "C" void kernel_launch(void* const* d_in, const int* in_sizes, int n_in,
                              void* d_out, int out_size) {
    const int4*  bits4  = (const int4*)d_in[0];
    const float* tables = (const float*)d_in[1];
    float4*      out4   = (float4*)d_out;

    int nquads = in_sizes[0] / 4;      // 16777216

    pack_tables_kernel<<<(NWORDS * 32 + 255) / 256, 256>>>(tables);

    cudaLaunchConfig_t cfg = {};
    cfg.gridDim  = dim3(MAP_BLOCKS, 1, 1);
    cfg.blockDim = dim3(MAP_THREADS, 1, 1);
    cfg.dynamicSmemBytes = 0;
    cfg.stream = 0;                    // legacy default stream (capture target)
    cudaLaunchAttribute attr[1];
    attr[0].id = cudaLaunchAttributeProgrammaticStreamSerialization;
    attr[0].val.programmaticStreamSerializationAllowed = 1;
    cfg.attrs = attr;
    cfg.numAttrs = 1;
    cudaLaunchKernelEx(&cfg, map_kernel, bits4, out4, nquads);
}